// round 1
// baseline (speedup 1.0000x reference)
#include <cuda_runtime.h>
#include <cuda_bf16.h>

#define N_NODES 8192
#define D_IN    512
#define H1      32
#define H2      16
#define E_EDGES 262144

// -------- scratch (device globals: no allocation allowed) --------
__device__ float g_xw0[N_NODES * H1];   // X @ W0
__device__ float g_h1 [N_NODES * H1];   // spmm1 accum (pre-relu)
__device__ float g_hw1[N_NODES * H2];   // relu(h1) @ W1
__device__ float g_mean[N_NODES * H2];  // spmm2 accum

// -------- zero accumulators (graph replays reuse globals) --------
__global__ void k_zero() {
    int gid = blockIdx.x * 256 + threadIdx.x;
    if (gid < N_NODES * H1) g_h1[gid] = 0.0f;
    if (gid < N_NODES * H2) g_mean[gid] = 0.0f;
}

// -------- K1: g_xw0 = X @ W0   [8192,512]x[512,32] --------
// Block: 256 thr (8 warps), 32 rows per block. X tile staged transposed in smem,
// each warp owns 4 rows (float4 broadcast read), lane = output column.
__global__ void k_xw0(const float* __restrict__ X, const float* __restrict__ W0) {
    __shared__ float sXT[128][36];   // [k][row_local], stride 36 -> 16B aligned rows
    __shared__ float sW [128][32];   // [k][col]
    const int tid  = threadIdx.x;
    const int lane = tid & 31;
    const int wid  = tid >> 5;
    const int row0 = blockIdx.x * 32;
    float acc[4] = {0.f, 0.f, 0.f, 0.f};

    for (int k0 = 0; k0 < D_IN; k0 += 128) {
        for (int idx = tid; idx < 128 * 32; idx += 256)
            sW[idx >> 5][idx & 31] = W0[(k0 + (idx >> 5)) * H1 + (idx & 31)];
        for (int idx = tid; idx < 32 * 128; idx += 256) {
            int r = idx >> 7, kk = idx & 127;
            sXT[kk][r] = X[(row0 + r) * D_IN + k0 + kk];
        }
        __syncthreads();
        const int rbase = wid * 4;
        #pragma unroll 8
        for (int kk = 0; kk < 128; kk++) {
            float w = sW[kk][lane];
            float4 xv = *reinterpret_cast<const float4*>(&sXT[kk][rbase]);
            acc[0] = fmaf(xv.x, w, acc[0]);
            acc[1] = fmaf(xv.y, w, acc[1]);
            acc[2] = fmaf(xv.z, w, acc[2]);
            acc[3] = fmaf(xv.w, w, acc[3]);
        }
        __syncthreads();
    }
    #pragma unroll
    for (int r = 0; r < 4; r++)
        g_xw0[(row0 + wid * 4 + r) * H1 + lane] = acc[r];
}

// -------- K2: spmm1: g_h1[row] += val * g_xw0[col]  (32 cols/edge) --------
__global__ void k_spmm1(const int* __restrict__ erow, const int* __restrict__ ecol,
                        const float* __restrict__ eval) {
    int gid = blockIdx.x * 256 + threadIdx.x;      // E * 32 threads
    int e = gid >> 5, c = gid & 31;
    if (e >= E_EDGES) return;
    int r  = erow[e];
    int cl = ecol[e];
    float v = eval[e];
    atomicAdd(&g_h1[r * H1 + c], v * g_xw0[cl * H1 + c]);
}

// -------- K3: g_hw1 = relu(g_h1) @ W1   [8192,32]x[32,16] --------
__global__ void k_hw1(const float* __restrict__ W1) {
    int gid = blockIdx.x * 256 + threadIdx.x;      // 8192*16
    if (gid >= N_NODES * H2) return;
    int row = gid >> 4, c = gid & 15;
    float acc = 0.f;
    #pragma unroll
    for (int k = 0; k < H1; k++)
        acc = fmaf(fmaxf(g_h1[row * H1 + k], 0.0f), __ldg(&W1[k * H2 + c]), acc);
    g_hw1[gid] = acc;
}

// -------- K4: spmm2: g_mean[row] += val * g_hw1[col]  (16 cols/edge) --------
__global__ void k_spmm2(const int* __restrict__ erow, const int* __restrict__ ecol,
                        const float* __restrict__ eval) {
    int gid = blockIdx.x * 256 + threadIdx.x;      // E * 16 threads
    int e = gid >> 4, c = gid & 15;
    if (e >= E_EDGES) return;
    int r  = erow[e];
    int cl = ecol[e];
    float v = eval[e];
    atomicAdd(&g_mean[r * H2 + c], v * g_hw1[cl * H2 + c]);
}

// -------- fast sigmoid: FMA/ALU pipes only (no MUFU) --------
// sigma(x): e = 2^(-|x|*log2e) via round-to-mantissa + deg-5 Horner; r = 1/(1+e)
// via magic-constant + 2 Newton. x>0 -> r ; x<=0 -> e*r. abs err < ~1e-5.
__device__ __forceinline__ float fast_sigmoid(float x) {
    float t = fmaxf(fabsf(x) * -1.4426950408889634f, -126.0f);
    float z = t + 12582912.0f;                 // 1.5*2^23: round-to-int in mantissa
    int   i = __float_as_int(z);
    float f = t - (z - 12582912.0f);           // frac in [-0.5, 0.5]
    float p = 1.3333558146e-3f;
    p = fmaf(p, f, 9.6181291076e-3f);
    p = fmaf(p, f, 5.5504108665e-2f);
    p = fmaf(p, f, 2.4022650696e-1f);
    p = fmaf(p, f, 6.9314718056e-1f);
    p = fmaf(p, f, 1.0f);
    float e = __int_as_float(__float_as_int(p) + (i << 23));   // e = 2^t = exp(-|x|)
    float d = 1.0f + e;                                        // d in (1,2]
    float r = __int_as_float(0x7EF127EA - __float_as_int(d));  // ~1/d (±3%)
    r = r * (2.0f - d * r);
    r = r * (2.0f - d * r);                                    // rel err ~1e-6
    float s = e * r;                                           // sigmoid(-|x|)
    return (x > 0.0f) ? r : s;                                 // 1-s == r exactly
}

// -------- K5: decode A = sigmoid(Z Z^T), Z = max(mean, 1e-32) --------
// 128x128 tile per block, 16x16 threads, 8x8 per thread. Upper triangle only,
// mirror-stored (A symmetric).
__global__ void k_decode(float* __restrict__ out) {
    const int bi = blockIdx.y, bj = blockIdx.x;
    if (bi > bj) return;
    __shared__ float sA[H2][132];
    __shared__ float sB[H2][132];
    const int tid = threadIdx.x;
    const int i0 = bi * 128, j0 = bj * 128;

    for (int idx = tid; idx < 128 * H2; idx += 256) {
        int r = idx >> 4, c = idx & 15;
        sA[c][r] = fmaxf(g_mean[(i0 + r) * H2 + c], 1e-32f);
        sB[c][r] = fmaxf(g_mean[(j0 + r) * H2 + c], 1e-32f);
    }
    __syncthreads();

    const int tx = tid & 15, ty = tid >> 4;
    float acc[8][8];
    #pragma unroll
    for (int ii = 0; ii < 8; ii++)
        #pragma unroll
        for (int jj = 0; jj < 8; jj++) acc[ii][jj] = 0.f;

    #pragma unroll
    for (int k = 0; k < H2; k++) {
        float4 a0 = *reinterpret_cast<const float4*>(&sA[k][ty * 8]);
        float4 a1 = *reinterpret_cast<const float4*>(&sA[k][ty * 8 + 4]);
        float4 b0 = *reinterpret_cast<const float4*>(&sB[k][tx * 8]);
        float4 b1 = *reinterpret_cast<const float4*>(&sB[k][tx * 8 + 4]);
        float a[8] = {a0.x, a0.y, a0.z, a0.w, a1.x, a1.y, a1.z, a1.w};
        float b[8] = {b0.x, b0.y, b0.z, b0.w, b1.x, b1.y, b1.z, b1.w};
        #pragma unroll
        for (int ii = 0; ii < 8; ii++)
            #pragma unroll
            for (int jj = 0; jj < 8; jj++)
                acc[ii][jj] = fmaf(a[ii], b[jj], acc[ii][jj]);
    }

    #pragma unroll
    for (int ii = 0; ii < 8; ii++)
        #pragma unroll
        for (int jj = 0; jj < 8; jj++)
            acc[ii][jj] = fast_sigmoid(acc[ii][jj]);

    // normal store (tile bi,bj)
    #pragma unroll
    for (int ii = 0; ii < 8; ii++) {
        int gi = i0 + ty * 8 + ii;
        float4 o0 = {acc[ii][0], acc[ii][1], acc[ii][2], acc[ii][3]};
        float4 o1 = {acc[ii][4], acc[ii][5], acc[ii][6], acc[ii][7]};
        float* dst = out + (size_t)gi * N_NODES + j0 + tx * 8;
        *reinterpret_cast<float4*>(dst)     = o0;
        *reinterpret_cast<float4*>(dst + 4) = o1;
    }
    // mirrored store (tile bj,bi) — 32B sector-aligned chunks
    if (bi != bj) {
        #pragma unroll
        for (int jj = 0; jj < 8; jj++) {
            int gj = j0 + tx * 8 + jj;
            float4 o0 = {acc[0][jj], acc[1][jj], acc[2][jj], acc[3][jj]};
            float4 o1 = {acc[4][jj], acc[5][jj], acc[6][jj], acc[7][jj]};
            float* dst = out + (size_t)gj * N_NODES + i0 + ty * 8;
            *reinterpret_cast<float4*>(dst)     = o0;
            *reinterpret_cast<float4*>(dst + 4) = o1;
        }
    }
}

extern "C" void kernel_launch(void* const* d_in, const int* in_sizes, int n_in,
                              void* d_out, int out_size) {
    const float* X    = (const float*)d_in[0];
    const int*   erow = (const int*)  d_in[1];
    const int*   ecol = (const int*)  d_in[2];
    const float* ev   = (const float*)d_in[3];
    const float* W0   = (const float*)d_in[4];
    const float* W1   = (const float*)d_in[5];
    // d_in[6] (W2) unused: std branch is dead in eval path (Z = mean)
    float* out = (float*)d_out;

    k_zero <<<(N_NODES * H1 + 255) / 256, 256>>>();
    k_xw0  <<<N_NODES / 32, 256>>>(X, W0);
    k_spmm1<<<(E_EDGES * H1) / 256, 256>>>(erow, ecol, ev);
    k_hw1  <<<(N_NODES * H2) / 256, 256>>>(W1);
    k_spmm2<<<(E_EDGES * H2) / 256, 256>>>(erow, ecol, ev);
    dim3 grid(N_NODES / 128, N_NODES / 128);
    k_decode<<<grid, 256>>>(out);
}

// round 3
// speedup vs baseline: 1.0916x; 1.0916x over previous
#include <cuda_runtime.h>
#include <cuda_bf16.h>

#define N_NODES 8192
#define D_IN    512
#define H1      32
#define H2      16
#define E_EDGES 262144

// -------- device-global scratch (no allocation allowed) --------
__device__ float g_xw0 [N_NODES * H1];   // X @ W0
__device__ float g_hw1 [N_NODES * H2];   // relu(spmm1) @ W1
__device__ float g_mean[N_NODES * H2];   // spmm2 result
__device__ int   g_cnt [N_NODES];        // row histogram
__device__ int   g_off [N_NODES + 1];    // CSR offsets
__device__ int   g_cur [N_NODES];        // scatter cursors
__device__ int   g_scol[E_EDGES];        // sorted cols
__device__ float g_sval[E_EDGES];        // sorted vals

// ===================== CSR build =====================
__global__ void k_zcnt() {
    int i = blockIdx.x * 256 + threadIdx.x;
    if (i < N_NODES) g_cnt[i] = 0;
}

__global__ void k_hist(const int* __restrict__ erow) {
    int e = blockIdx.x * 256 + threadIdx.x;
    if (e < E_EDGES) atomicAdd(&g_cnt[erow[e]], 1);
}

// single-block scan over 8192 counts (8 per thread, 1024 threads)
__global__ void k_scan() {
    __shared__ int s[1024];
    const int t = threadIdx.x;
    const int base = t * 8;
    int loc[8], sum = 0;
    #pragma unroll
    for (int i = 0; i < 8; i++) { loc[i] = g_cnt[base + i]; sum += loc[i]; }
    s[t] = sum;
    __syncthreads();
    for (int d = 1; d < 1024; d <<= 1) {
        int v = (t >= d) ? s[t - d] : 0;
        __syncthreads();
        s[t] += v;
        __syncthreads();
    }
    int run = s[t] - sum;               // exclusive prefix
    #pragma unroll
    for (int i = 0; i < 8; i++) {
        g_off[base + i] = run;
        g_cur[base + i] = run;
        run += loc[i];
    }
    if (t == 1023) g_off[N_NODES] = run;
}

__global__ void k_scatter(const int* __restrict__ erow, const int* __restrict__ ecol,
                          const float* __restrict__ eval) {
    int e = blockIdx.x * 256 + threadIdx.x;
    if (e >= E_EDGES) return;
    int r = erow[e];
    int p = atomicAdd(&g_cur[r], 1);
    g_scol[p] = ecol[e];
    g_sval[p] = eval[e];
}

// ===================== K1: g_xw0 = X @ W0 =====================
__global__ void k_xw0(const float* __restrict__ X, const float* __restrict__ W0) {
    __shared__ float sXT[128][36];
    __shared__ float sW [128][32];
    const int tid  = threadIdx.x;
    const int lane = tid & 31;
    const int wid  = tid >> 5;
    const int row0 = blockIdx.x * 32;
    float acc[4] = {0.f, 0.f, 0.f, 0.f};

    for (int k0 = 0; k0 < D_IN; k0 += 128) {
        for (int idx = tid; idx < 128 * 32; idx += 256)
            sW[idx >> 5][idx & 31] = W0[(k0 + (idx >> 5)) * H1 + (idx & 31)];
        for (int idx = tid; idx < 32 * 128; idx += 256) {
            int r = idx >> 7, kk = idx & 127;
            sXT[kk][r] = X[(row0 + r) * D_IN + k0 + kk];
        }
        __syncthreads();
        const int rbase = wid * 4;
        #pragma unroll 8
        for (int kk = 0; kk < 128; kk++) {
            float w = sW[kk][lane];
            float4 xv = *reinterpret_cast<const float4*>(&sXT[kk][rbase]);
            acc[0] = fmaf(xv.x, w, acc[0]);
            acc[1] = fmaf(xv.y, w, acc[1]);
            acc[2] = fmaf(xv.z, w, acc[2]);
            acc[3] = fmaf(xv.w, w, acc[3]);
        }
        __syncthreads();
    }
    #pragma unroll
    for (int r = 0; r < 4; r++)
        g_xw0[(row0 + wid * 4 + r) * H1 + lane] = acc[r];
}

// ===================== K2: fused spmm1 + relu + @W1 =====================
// warp per row: lane = H1 column; register accumulation, no atomics.
__global__ void k_spmm1_hw1(const float* __restrict__ W1) {
    __shared__ float sW1[H1][H2];      // 32x16
    __shared__ float sH[8][H1];        // per-warp relu'd h1 row
    const int tid  = threadIdx.x;
    const int lane = tid & 31;
    const int wid  = tid >> 5;
    for (int idx = tid; idx < H1 * H2; idx += 256)
        sW1[idx >> 4][idx & 15] = W1[idx];
    __syncthreads();

    const int row = blockIdx.x * 8 + wid;
    const int beg = g_off[row], end = g_off[row + 1];
    float acc = 0.f;
    for (int e0 = beg; e0 < end; e0 += 32) {
        int ee = e0 + lane;
        int   c = (ee < end) ? g_scol[ee] : 0;
        float v = (ee < end) ? g_sval[ee] : 0.f;
        int m = min(32, end - e0);   // warp-uniform
        for (int j = 0; j < m; j++) {
            int   cj = __shfl_sync(0xFFFFFFFFu, c, j);
            float vj = __shfl_sync(0xFFFFFFFFu, v, j);
            acc = fmaf(vj, g_xw0[cj * H1 + lane], acc);
        }
    }
    sH[wid][lane] = fmaxf(acc, 0.0f);
    __syncwarp();
    if (lane < H2) {
        float o = 0.f;
        #pragma unroll
        for (int k = 0; k < H1; k++)
            o = fmaf(sH[wid][k], sW1[k][lane], o);
        g_hw1[row * H2 + lane] = o;
    }
}

// ===================== K3: spmm2 (warp per row, 2 edges/iter) =====================
__global__ void k_spmm2() {
    const int tid  = threadIdx.x;
    const int lane = tid & 31;
    const int wid  = tid >> 5;
    const int half = lane >> 4;        // 0 or 1
    const int col  = lane & 15;

    const int row = blockIdx.x * 8 + wid;
    const int beg = g_off[row], end = g_off[row + 1];
    float acc = 0.f;
    for (int e0 = beg; e0 < end; e0 += 32) {
        int ee = e0 + lane;
        int   c = (ee < end) ? g_scol[ee] : 0;
        float v = (ee < end) ? g_sval[ee] : 0.f;   // zero-filled tail
        int m  = min(32, end - e0);
        int mp = (m + 1) & ~1;          // pad to even: both halves run mp/2 iters,
                                        // padded slot has v=0 so fma is a no-op.
        for (int j = half; j < mp; j += 2) {
            int   cj = __shfl_sync(0xFFFFFFFFu, c, j);
            float vj = __shfl_sync(0xFFFFFFFFu, v, j);
            acc = fmaf(vj, g_hw1[cj * H2 + col], acc);
        }
    }
    acc += __shfl_xor_sync(0xFFFFFFFFu, acc, 16);
    if (lane < H2) g_mean[row * H2 + lane] = acc;
}

// ===================== fast sigmoid (FMA/ALU pipes only) =====================
__device__ __forceinline__ float fast_sigmoid(float x) {
    float t = fmaxf(fabsf(x) * -1.4426950408889634f, -126.0f);
    float z = t + 12582912.0f;
    int   i = __float_as_int(z);
    float f = t - (z - 12582912.0f);
    float p = 1.3333558146e-3f;
    p = fmaf(p, f, 9.6181291076e-3f);
    p = fmaf(p, f, 5.5504108665e-2f);
    p = fmaf(p, f, 2.4022650696e-1f);
    p = fmaf(p, f, 6.9314718056e-1f);
    p = fmaf(p, f, 1.0f);
    float e = __int_as_float(__float_as_int(p) + (i << 23));   // exp(-|x|)
    float d = 1.0f + e;
    float r = __int_as_float(0x7EF127EA - __float_as_int(d));
    r = r * (2.0f - d * r);
    r = r * (2.0f - d * r);
    float s = e * r;
    return (x > 0.0f) ? r : s;
}

// ===================== K4: decode A = sigmoid(Z Z^T) =====================
__global__ __launch_bounds__(256) void k_decode(float* __restrict__ out) {
    const int bi = blockIdx.y, bj = blockIdx.x;
    if (bi > bj) return;
    __shared__ float sA[H2][132];
    __shared__ float sB[H2][132];
    const int tid = threadIdx.x;
    const int i0 = bi * 128, j0 = bj * 128;

    for (int idx = tid; idx < 128 * H2; idx += 256) {
        int r = idx >> 4, c = idx & 15;
        sA[c][r] = fmaxf(g_mean[(i0 + r) * H2 + c], 1e-32f);
        sB[c][r] = fmaxf(g_mean[(j0 + r) * H2 + c], 1e-32f);
    }
    __syncthreads();

    const int tx = tid & 15, ty = tid >> 4;
    float acc[8][8];
    #pragma unroll
    for (int ii = 0; ii < 8; ii++)
        #pragma unroll
        for (int jj = 0; jj < 8; jj++) acc[ii][jj] = 0.f;

    #pragma unroll
    for (int k = 0; k < H2; k++) {
        float4 a0 = *reinterpret_cast<const float4*>(&sA[k][ty * 8]);
        float4 a1 = *reinterpret_cast<const float4*>(&sA[k][ty * 8 + 4]);
        float4 b0 = *reinterpret_cast<const float4*>(&sB[k][tx * 8]);
        float4 b1 = *reinterpret_cast<const float4*>(&sB[k][tx * 8 + 4]);
        float a[8] = {a0.x, a0.y, a0.z, a0.w, a1.x, a1.y, a1.z, a1.w};
        float b[8] = {b0.x, b0.y, b0.z, b0.w, b1.x, b1.y, b1.z, b1.w};
        #pragma unroll
        for (int ii = 0; ii < 8; ii++)
            #pragma unroll
            for (int jj = 0; jj < 8; jj++)
                acc[ii][jj] = fmaf(a[ii], b[jj], acc[ii][jj]);
    }

    #pragma unroll
    for (int ii = 0; ii < 8; ii++)
        #pragma unroll
        for (int jj = 0; jj < 8; jj++)
            acc[ii][jj] = fast_sigmoid(acc[ii][jj]);

    // normal tile (bi,bj) — streaming stores, nothing re-reads out
    #pragma unroll
    for (int ii = 0; ii < 8; ii++) {
        int gi = i0 + ty * 8 + ii;
        float4 o0 = {acc[ii][0], acc[ii][1], acc[ii][2], acc[ii][3]};
        float4 o1 = {acc[ii][4], acc[ii][5], acc[ii][6], acc[ii][7]};
        float* dst = out + (size_t)gi * N_NODES + j0 + tx * 8;
        __stcs(reinterpret_cast<float4*>(dst),     o0);
        __stcs(reinterpret_cast<float4*>(dst + 4), o1);
    }
    // mirrored tile (bj,bi)
    if (bi != bj) {
        #pragma unroll
        for (int jj = 0; jj < 8; jj++) {
            int gj = j0 + tx * 8 + jj;
            float4 o0 = {acc[0][jj], acc[1][jj], acc[2][jj], acc[3][jj]};
            float4 o1 = {acc[4][jj], acc[5][jj], acc[6][jj], acc[7][jj]};
            float* dst = out + (size_t)gj * N_NODES + i0 + ty * 8;
            __stcs(reinterpret_cast<float4*>(dst),     o0);
            __stcs(reinterpret_cast<float4*>(dst + 4), o1);
        }
    }
}

extern "C" void kernel_launch(void* const* d_in, const int* in_sizes, int n_in,
                              void* d_out, int out_size) {
    const float* X    = (const float*)d_in[0];
    const int*   erow = (const int*)  d_in[1];
    const int*   ecol = (const int*)  d_in[2];
    const float* ev   = (const float*)d_in[3];
    const float* W0   = (const float*)d_in[4];
    const float* W1   = (const float*)d_in[5];
    // d_in[6] (W2) unused: std branch is dead in eval (Z = mean)
    float* out = (float*)d_out;

    k_zcnt    <<<(N_NODES + 255) / 256, 256>>>();
    k_hist    <<<E_EDGES / 256, 256>>>(erow);
    k_scan    <<<1, 1024>>>();
    k_scatter <<<E_EDGES / 256, 256>>>(erow, ecol, ev);
    k_xw0     <<<N_NODES / 32, 256>>>(X, W0);
    k_spmm1_hw1<<<N_NODES / 8, 256>>>(W1);
    k_spmm2   <<<N_NODES / 8, 256>>>();
    dim3 grid(N_NODES / 128, N_NODES / 128);
    k_decode  <<<grid, 256>>>(out);
}

// round 4
// speedup vs baseline: 1.1663x; 1.0685x over previous
#include <cuda_runtime.h>
#include <cuda_bf16.h>

#define N_NODES 8192
#define D_IN    512
#define H1      32
#define H2      16
#define E_EDGES 262144

// -------- device-global scratch (no allocation allowed) --------
__device__ float g_xw0 [N_NODES * H1];   // X @ W0
__device__ float g_hw1 [N_NODES * H2];   // relu(spmm1) @ W1
__device__ float g_mean[N_NODES * H2];   // spmm2 result
__device__ int   g_cnt [N_NODES];        // row histogram (zeroed at end of each run)
__device__ int   g_off [N_NODES + 1];    // CSR offsets
__device__ int   g_cur [N_NODES];        // scatter cursors
__device__ int2  g_edge[E_EDGES];        // (col, val bits) interleaved

// ===================== CSR build =====================
__global__ void k_hist(const int* __restrict__ erow) {
    int e = blockIdx.x * 256 + threadIdx.x;
    if (e < E_EDGES) atomicAdd(&g_cnt[erow[e]], 1);
}

// single-block scan over 8192 counts (8 per thread, 1024 threads)
__global__ void k_scan() {
    __shared__ int s[1024];
    const int t = threadIdx.x;
    const int base = t * 8;
    int loc[8], sum = 0;
    #pragma unroll
    for (int i = 0; i < 8; i++) { loc[i] = g_cnt[base + i]; sum += loc[i]; }
    s[t] = sum;
    __syncthreads();
    for (int d = 1; d < 1024; d <<= 1) {
        int v = (t >= d) ? s[t - d] : 0;
        __syncthreads();
        s[t] += v;
        __syncthreads();
    }
    int run = s[t] - sum;               // exclusive prefix
    #pragma unroll
    for (int i = 0; i < 8; i++) {
        g_off[base + i] = run;
        g_cur[base + i] = run;
        run += loc[i];
    }
    if (t == 1023) g_off[N_NODES] = run;
}

__global__ void k_scatter(const int* __restrict__ erow, const int* __restrict__ ecol,
                          const float* __restrict__ eval) {
    int e = blockIdx.x * 256 + threadIdx.x;
    if (e >= E_EDGES) return;
    int r = erow[e];
    int p = atomicAdd(&g_cur[r], 1);
    g_edge[p] = make_int2(ecol[e], __float_as_int(eval[e]));
    // cnt is dead after k_scan: re-zero it here for the next graph replay
    // (device globals start zero-initialized, so the first run is correct too)
    if (e < N_NODES) g_cnt[e] = 0;
}

// ===================== K1: g_xw0 = X @ W0 =====================
__global__ void k_xw0(const float* __restrict__ X, const float* __restrict__ W0) {
    __shared__ float sXT[128][36];
    __shared__ float sW [128][32];
    const int tid  = threadIdx.x;
    const int lane = tid & 31;
    const int wid  = tid >> 5;
    const int row0 = blockIdx.x * 32;
    float acc[4] = {0.f, 0.f, 0.f, 0.f};

    for (int k0 = 0; k0 < D_IN; k0 += 128) {
        for (int idx = tid; idx < 128 * 32; idx += 256)
            sW[idx >> 5][idx & 31] = W0[(k0 + (idx >> 5)) * H1 + (idx & 31)];
        for (int idx = tid; idx < 32 * 128; idx += 256) {
            int r = idx >> 7, kk = idx & 127;
            sXT[kk][r] = X[(row0 + r) * D_IN + k0 + kk];
        }
        __syncthreads();
        const int rbase = wid * 4;
        #pragma unroll 8
        for (int kk = 0; kk < 128; kk++) {
            float w = sW[kk][lane];
            float4 xv = *reinterpret_cast<const float4*>(&sXT[kk][rbase]);
            acc[0] = fmaf(xv.x, w, acc[0]);
            acc[1] = fmaf(xv.y, w, acc[1]);
            acc[2] = fmaf(xv.z, w, acc[2]);
            acc[3] = fmaf(xv.w, w, acc[3]);
        }
        __syncthreads();
    }
    #pragma unroll
    for (int r = 0; r < 4; r++)
        g_xw0[(row0 + wid * 4 + r) * H1 + lane] = acc[r];
}

// ===================== K2: fused spmm1 + relu + @W1 =====================
// warp per row: lane = H1 column; register accumulation, no atomics.
__global__ void k_spmm1_hw1(const float* __restrict__ W1) {
    __shared__ float sW1[H1][H2];      // 32x16
    __shared__ float sH[8][H1];        // per-warp relu'd h1 row
    const int tid  = threadIdx.x;
    const int lane = tid & 31;
    const int wid  = tid >> 5;
    for (int idx = tid; idx < H1 * H2; idx += 256)
        sW1[idx >> 4][idx & 15] = W1[idx];
    __syncthreads();

    const int row = blockIdx.x * 8 + wid;
    const int beg = g_off[row], end = g_off[row + 1];
    float acc = 0.f;
    for (int e0 = beg; e0 < end; e0 += 32) {
        int ee = e0 + lane;
        int2 ed = (ee < end) ? g_edge[ee] : make_int2(0, 0);
        int m = min(32, end - e0);   // warp-uniform
        for (int j = 0; j < m; j++) {
            int   cj = __shfl_sync(0xFFFFFFFFu, ed.x, j);
            float vj = __int_as_float(__shfl_sync(0xFFFFFFFFu, ed.y, j));
            acc = fmaf(vj, g_xw0[cj * H1 + lane], acc);
        }
    }
    sH[wid][lane] = fmaxf(acc, 0.0f);
    __syncwarp();
    if (lane < H2) {
        float o = 0.f;
        #pragma unroll
        for (int k = 0; k < H1; k++)
            o = fmaf(sH[wid][k], sW1[k][lane], o);
        g_hw1[row * H2 + lane] = o;
    }
}

// ===================== K3: spmm2 (warp per row, 2 edges/iter) =====================
__global__ void k_spmm2() {
    const int tid  = threadIdx.x;
    const int lane = tid & 31;
    const int wid  = tid >> 5;
    const int half = lane >> 4;        // 0 or 1
    const int col  = lane & 15;

    const int row = blockIdx.x * 8 + wid;
    const int beg = g_off[row], end = g_off[row + 1];
    float acc = 0.f;
    for (int e0 = beg; e0 < end; e0 += 32) {
        int ee = e0 + lane;
        int2 ed = (ee < end) ? g_edge[ee] : make_int2(0, 0);  // zero-filled tail
        int m  = min(32, end - e0);
        int mp = (m + 1) & ~1;          // pad to even: both halves run mp/2 iters,
                                        // padded slot has v=0 so fma is a no-op.
        for (int j = half; j < mp; j += 2) {
            int   cj = __shfl_sync(0xFFFFFFFFu, ed.x, j);
            float vj = __int_as_float(__shfl_sync(0xFFFFFFFFu, ed.y, j));
            acc = fmaf(vj, g_hw1[cj * H2 + col], acc);
        }
    }
    acc += __shfl_xor_sync(0xFFFFFFFFu, acc, 16);
    if (lane < H2) g_mean[row * H2 + lane] = acc;
}

// ===================== fast sigmoid: MUFU ex2 + MUFU rcp =====================
// e = 2^(-|x|*log2e) in (0,1]; d = 1+e in (1,2]; rcp.approx ~1ulp there.
// x>0 -> 1/(1+e); x<=0 -> e/(1+e). Error ~1e-7, far below 1e-3 tolerance.
__device__ __forceinline__ float fast_sigmoid(float x) {
    float t = fabsf(x) * -1.4426950408889634f;
    float e; asm("ex2.approx.f32 %0, %1;" : "=f"(e) : "f"(t));
    float d = 1.0f + e;
    float r; asm("rcp.approx.f32 %0, %1;" : "=f"(r) : "f"(d));
    return (x > 0.0f) ? r : e * r;
}

// ===================== K4: decode A = sigmoid(Z Z^T) =====================
// triangular 1-D grid: 2080 blocks, each does tile (bi,bj) with bi<=bj and its mirror
__global__ __launch_bounds__(256) void k_decode(float* __restrict__ out) {
    // map linear t -> (i,j) with 0 <= j <= i < 64, then bi=j, bj=i
    const int t = blockIdx.x;
    int i = (int)((sqrtf(8.0f * (float)t + 1.0f) - 1.0f) * 0.5f);
    int j = t - ((i * (i + 1)) >> 1);
    if (j < 0)  { i--; j = t - ((i * (i + 1)) >> 1); }
    if (j > i)  { i++; j = t - ((i * (i + 1)) >> 1); }
    const int bi = j, bj = i;

    __shared__ float sA[H2][132];
    __shared__ float sB[H2][132];
    const int tid = threadIdx.x;
    const int i0 = bi * 128, j0 = bj * 128;

    for (int idx = tid; idx < 128 * H2; idx += 256) {
        int r = idx >> 4, c = idx & 15;
        sA[c][r] = fmaxf(g_mean[(i0 + r) * H2 + c], 1e-32f);
        sB[c][r] = fmaxf(g_mean[(j0 + r) * H2 + c], 1e-32f);
    }
    __syncthreads();

    const int tx = tid & 15, ty = tid >> 4;
    float acc[8][8];
    #pragma unroll
    for (int ii = 0; ii < 8; ii++)
        #pragma unroll
        for (int jj = 0; jj < 8; jj++) acc[ii][jj] = 0.f;

    #pragma unroll
    for (int k = 0; k < H2; k++) {
        float4 a0 = *reinterpret_cast<const float4*>(&sA[k][ty * 8]);
        float4 a1 = *reinterpret_cast<const float4*>(&sA[k][ty * 8 + 4]);
        float4 b0 = *reinterpret_cast<const float4*>(&sB[k][tx * 8]);
        float4 b1 = *reinterpret_cast<const float4*>(&sB[k][tx * 8 + 4]);
        float a[8] = {a0.x, a0.y, a0.z, a0.w, a1.x, a1.y, a1.z, a1.w};
        float b[8] = {b0.x, b0.y, b0.z, b0.w, b1.x, b1.y, b1.z, b1.w};
        #pragma unroll
        for (int ii = 0; ii < 8; ii++)
            #pragma unroll
            for (int jj = 0; jj < 8; jj++)
                acc[ii][jj] = fmaf(a[ii], b[jj], acc[ii][jj]);
    }

    #pragma unroll
    for (int ii = 0; ii < 8; ii++)
        #pragma unroll
        for (int jj = 0; jj < 8; jj++)
            acc[ii][jj] = fast_sigmoid(acc[ii][jj]);

    // normal tile (bi,bj) — streaming stores, nothing re-reads out
    #pragma unroll
    for (int ii = 0; ii < 8; ii++) {
        int gi = i0 + ty * 8 + ii;
        float4 o0 = {acc[ii][0], acc[ii][1], acc[ii][2], acc[ii][3]};
        float4 o1 = {acc[ii][4], acc[ii][5], acc[ii][6], acc[ii][7]};
        float* dst = out + (size_t)gi * N_NODES + j0 + tx * 8;
        __stcs(reinterpret_cast<float4*>(dst),     o0);
        __stcs(reinterpret_cast<float4*>(dst + 4), o1);
    }
    // mirrored tile (bj,bi)
    if (bi != bj) {
        #pragma unroll
        for (int jj = 0; jj < 8; jj++) {
            int gj = j0 + tx * 8 + jj;
            float4 o0 = {acc[0][jj], acc[1][jj], acc[2][jj], acc[3][jj]};
            float4 o1 = {acc[4][jj], acc[5][jj], acc[6][jj], acc[7][jj]};
            float* dst = out + (size_t)gj * N_NODES + i0 + ty * 8;
            __stcs(reinterpret_cast<float4*>(dst),     o0);
            __stcs(reinterpret_cast<float4*>(dst + 4), o1);
        }
    }
}

extern "C" void kernel_launch(void* const* d_in, const int* in_sizes, int n_in,
                              void* d_out, int out_size) {
    const float* X    = (const float*)d_in[0];
    const int*   erow = (const int*)  d_in[1];
    const int*   ecol = (const int*)  d_in[2];
    const float* ev   = (const float*)d_in[3];
    const float* W0   = (const float*)d_in[4];
    const float* W1   = (const float*)d_in[5];
    // d_in[6] (W2) unused: std branch is dead in eval (Z = mean)
    float* out = (float*)d_out;

    k_hist    <<<E_EDGES / 256, 256>>>(erow);
    k_scan    <<<1, 1024>>>();
    k_scatter <<<E_EDGES / 256, 256>>>(erow, ecol, ev);
    k_xw0     <<<N_NODES / 32, 256>>>(X, W0);
    k_spmm1_hw1<<<N_NODES / 8, 256>>>(W1);
    k_spmm2   <<<N_NODES / 8, 256>>>();
    const int NT = 64 * 65 / 2;   // 2080 triangular tiles
    k_decode  <<<NT, 256>>>(out);
}

// round 5
// speedup vs baseline: 1.2351x; 1.0590x over previous
#include <cuda_runtime.h>
#include <cuda_bf16.h>

#define N_NODES 8192
#define D_IN    512
#define H1      32
#define H2      16
#define E_EDGES 262144

typedef unsigned long long ull;

// -------- device-global scratch (no allocation allowed) --------
__device__ float g_xw0 [N_NODES * H1];   // X @ W0
__device__ float g_hw1 [N_NODES * H2];   // relu(spmm1) @ W1
__device__ float g_mean[N_NODES * H2];   // spmm2 result
__device__ int   g_cnt [N_NODES];        // row histogram (re-zeroed each run)
__device__ int   g_off [N_NODES + 1];    // CSR offsets
__device__ int   g_cur [N_NODES];        // scatter cursors
__device__ int2  g_edge[E_EDGES];        // (col, val bits) interleaved

// ===================== CSR build =====================
__global__ void k_hist(const int* __restrict__ erow) {
    int e = blockIdx.x * 256 + threadIdx.x;
    if (e < E_EDGES) atomicAdd(&g_cnt[erow[e]], 1);
}

__global__ void k_scan() {
    __shared__ int s[1024];
    const int t = threadIdx.x;
    const int base = t * 8;
    int loc[8], sum = 0;
    #pragma unroll
    for (int i = 0; i < 8; i++) { loc[i] = g_cnt[base + i]; sum += loc[i]; }
    s[t] = sum;
    __syncthreads();
    for (int d = 1; d < 1024; d <<= 1) {
        int v = (t >= d) ? s[t - d] : 0;
        __syncthreads();
        s[t] += v;
        __syncthreads();
    }
    int run = s[t] - sum;               // exclusive prefix
    #pragma unroll
    for (int i = 0; i < 8; i++) {
        g_off[base + i] = run;
        g_cur[base + i] = run;
        run += loc[i];
    }
    if (t == 1023) g_off[N_NODES] = run;
}

__global__ void k_scatter(const int* __restrict__ erow, const int* __restrict__ ecol,
                          const float* __restrict__ eval) {
    int e = blockIdx.x * 256 + threadIdx.x;
    if (e >= E_EDGES) return;
    int r = erow[e];
    int p = atomicAdd(&g_cur[r], 1);
    g_edge[p] = make_int2(ecol[e], __float_as_int(eval[e]));
    // cnt is dead after k_scan: re-zero for next replay (globals start zeroed)
    if (e < N_NODES) g_cnt[e] = 0;
}

// ===================== K1: g_xw0 = X @ W0 =====================
// 512 thr, 16 rows/block, grid 512. 16 warps = 4 row-groups x 4 k-quarters.
// Register accumulation per quarter, smem partial reduce at the end.
__global__ __launch_bounds__(512) void k_xw0(const float* __restrict__ X,
                                             const float* __restrict__ W0) {
    __shared__ float sX[16][132];       // chunk: 16 rows x 128 k (+pad, 16B aligned)
    __shared__ float sW[128][32];       // chunk: 128 k x 32 cols
    __shared__ float sP[4][16][32];     // partials [kq][row][col]
    const int tid  = threadIdx.x;
    const int lane = tid & 31;
    const int wid  = tid >> 5;
    const int rg   = wid & 3;           // row group (4 rows)
    const int kq   = wid >> 2;          // k quarter within chunk (32 k's)
    const int row0 = blockIdx.x * 16;

    float acc0 = 0.f, acc1 = 0.f, acc2 = 0.f, acc3 = 0.f;

    for (int k0 = 0; k0 < D_IN; k0 += 128) {
        // stage X chunk: warp = row, lane = k-float4 (global coalesced, smem conflict-free)
        {
            int r = wid;                 // 16 warps -> 16 rows
            float4 xv = *reinterpret_cast<const float4*>(
                &X[(size_t)(row0 + r) * D_IN + k0 + lane * 4]);
            *reinterpret_cast<float4*>(&sX[r][lane * 4]) = xv;
        }
        // stage W chunk: 1024 float4, 2 per thread, fully coalesced
        #pragma unroll
        for (int i = 0; i < 2; i++) {
            int idx = tid + i * 512;
            int kk = idx >> 3, c4 = idx & 7;
            *reinterpret_cast<float4*>(&sW[kk][c4 * 4]) =
                *reinterpret_cast<const float4*>(&W0[(size_t)(k0 + kk) * H1 + c4 * 4]);
        }
        __syncthreads();

        const float* xr0 = sX[rg * 4 + 0];
        const float* xr1 = sX[rg * 4 + 1];
        const float* xr2 = sX[rg * 4 + 2];
        const float* xr3 = sX[rg * 4 + 3];
        const int kb = kq * 32;
        #pragma unroll
        for (int kk = 0; kk < 32; kk += 4) {
            int k = kb + kk;
            float4 x0 = *reinterpret_cast<const float4*>(&xr0[k]);
            float4 x1 = *reinterpret_cast<const float4*>(&xr1[k]);
            float4 x2 = *reinterpret_cast<const float4*>(&xr2[k]);
            float4 x3 = *reinterpret_cast<const float4*>(&xr3[k]);
            float w0 = sW[k + 0][lane];
            float w1 = sW[k + 1][lane];
            float w2 = sW[k + 2][lane];
            float w3 = sW[k + 3][lane];
            acc0 = fmaf(x0.x, w0, fmaf(x0.y, w1, fmaf(x0.z, w2, fmaf(x0.w, w3, acc0))));
            acc1 = fmaf(x1.x, w0, fmaf(x1.y, w1, fmaf(x1.z, w2, fmaf(x1.w, w3, acc1))));
            acc2 = fmaf(x2.x, w0, fmaf(x2.y, w1, fmaf(x2.z, w2, fmaf(x2.w, w3, acc2))));
            acc3 = fmaf(x3.x, w0, fmaf(x3.y, w1, fmaf(x3.z, w2, fmaf(x3.w, w3, acc3))));
        }
        __syncthreads();
    }
    sP[kq][rg * 4 + 0][lane] = acc0;
    sP[kq][rg * 4 + 1][lane] = acc1;
    sP[kq][rg * 4 + 2][lane] = acc2;
    sP[kq][rg * 4 + 3][lane] = acc3;
    __syncthreads();
    int r = wid, c = lane;              // 512 threads = 16 rows x 32 cols
    g_xw0[(size_t)(row0 + r) * H1 + c] =
        (sP[0][r][c] + sP[1][r][c]) + (sP[2][r][c] + sP[3][r][c]);
}

// ===================== K2: fused spmm1 + relu + @W1 =====================
__global__ void k_spmm1_hw1(const float* __restrict__ W1) {
    __shared__ float sW1[H1][H2];
    __shared__ float sH[8][H1];
    const int tid  = threadIdx.x;
    const int lane = tid & 31;
    const int wid  = tid >> 5;
    for (int idx = tid; idx < H1 * H2; idx += 256)
        sW1[idx >> 4][idx & 15] = W1[idx];
    __syncthreads();

    const int row = blockIdx.x * 8 + wid;
    const int beg = g_off[row], end = g_off[row + 1];
    float acc = 0.f;
    for (int e0 = beg; e0 < end; e0 += 32) {
        int ee = e0 + lane;
        int2 ed = (ee < end) ? g_edge[ee] : make_int2(0, 0);
        int m = min(32, end - e0);   // warp-uniform
        for (int j = 0; j < m; j++) {
            int   cj = __shfl_sync(0xFFFFFFFFu, ed.x, j);
            float vj = __int_as_float(__shfl_sync(0xFFFFFFFFu, ed.y, j));
            acc = fmaf(vj, g_xw0[cj * H1 + lane], acc);
        }
    }
    sH[wid][lane] = fmaxf(acc, 0.0f);
    __syncwarp();
    if (lane < H2) {
        float o = 0.f;
        #pragma unroll
        for (int k = 0; k < H1; k++)
            o = fmaf(sH[wid][k], sW1[k][lane], o);
        g_hw1[row * H2 + lane] = o;
    }
}

// ===================== K3: spmm2 (warp per row, 2 edges/iter) =====================
__global__ void k_spmm2() {
    const int tid  = threadIdx.x;
    const int lane = tid & 31;
    const int wid  = tid >> 5;
    const int half = lane >> 4;
    const int col  = lane & 15;

    const int row = blockIdx.x * 8 + wid;
    const int beg = g_off[row], end = g_off[row + 1];
    float acc = 0.f;
    for (int e0 = beg; e0 < end; e0 += 32) {
        int ee = e0 + lane;
        int2 ed = (ee < end) ? g_edge[ee] : make_int2(0, 0);
        int m  = min(32, end - e0);
        int mp = (m + 1) & ~1;          // even trip count for both halves
        for (int j = half; j < mp; j += 2) {
            int   cj = __shfl_sync(0xFFFFFFFFu, ed.x, j);
            float vj = __int_as_float(__shfl_sync(0xFFFFFFFFu, ed.y, j));
            acc = fmaf(vj, g_hw1[cj * H2 + col], acc);
        }
    }
    acc += __shfl_xor_sync(0xFFFFFFFFu, acc, 16);
    if (lane < H2) g_mean[row * H2 + lane] = acc;
}

// ===================== fast sigmoid: MUFU ex2 + MUFU rcp =====================
__device__ __forceinline__ float fast_sigmoid(float x) {
    float t = fabsf(x) * -1.4426950408889634f;
    float e; asm("ex2.approx.f32 %0, %1;" : "=f"(e) : "f"(t));
    float d = 1.0f + e;
    float r; asm("rcp.approx.f32 %0, %1;" : "=f"(r) : "f"(d));
    return (x > 0.0f) ? r : e * r;
}

// packed fp32x2 fma (sm_103a FFMA2, PTX-only)
__device__ __forceinline__ ull ffma2(ull a, ull b, ull c) {
    ull d;
    asm("fma.rn.f32x2 %0, %1, %2, %3;" : "=l"(d) : "l"(a), "l"(b), "l"(c));
    return d;
}
__device__ __forceinline__ ull pack2(float lo, float hi) {
    ull d;
    asm("mov.b64 %0, {%1, %2};" : "=l"(d) : "r"(__float_as_uint(lo)), "r"(__float_as_uint(hi)));
    return d;
}

// ===================== K4: decode A = sigmoid(Z Z^T) =====================
// triangular 1-D grid: 2080 blocks, tile (bi,bj) bi<=bj plus its mirror.
__global__ __launch_bounds__(256) void k_decode(float* __restrict__ out) {
    const int t = blockIdx.x;
    int i = (int)((sqrtf(8.0f * (float)t + 1.0f) - 1.0f) * 0.5f);
    int j = t - ((i * (i + 1)) >> 1);
    if (j < 0)  { i--; j = t - ((i * (i + 1)) >> 1); }
    if (j > i)  { i++; j = t - ((i * (i + 1)) >> 1); }
    const int bi = j, bj = i;

    __shared__ float sA[H2][132];
    __shared__ float sB[H2][132];
    const int tid = threadIdx.x;
    const int i0 = bi * 128, j0 = bj * 128;

    for (int idx = tid; idx < 128 * H2; idx += 256) {
        int r = idx >> 4, c = idx & 15;
        sA[c][r] = fmaxf(g_mean[(i0 + r) * H2 + c], 1e-32f);
        sB[c][r] = fmaxf(g_mean[(j0 + r) * H2 + c], 1e-32f);
    }
    __syncthreads();

    const int tx = tid & 15, ty = tid >> 4;
    ull acc2[8][4];
    #pragma unroll
    for (int ii = 0; ii < 8; ii++)
        #pragma unroll
        for (int p = 0; p < 4; p++) acc2[ii][p] = 0ull;

    #pragma unroll
    for (int k = 0; k < H2; k++) {
        // b as packed pairs straight out of smem (LDS.128 -> 2 x f32x2 each)
        ulonglong2 bq0 = *reinterpret_cast<const ulonglong2*>(&sB[k][tx * 8]);
        ulonglong2 bq1 = *reinterpret_cast<const ulonglong2*>(&sB[k][tx * 8 + 4]);
        ull bp[4] = {bq0.x, bq0.y, bq1.x, bq1.y};
        float4 a0 = *reinterpret_cast<const float4*>(&sA[k][ty * 8]);
        float4 a1 = *reinterpret_cast<const float4*>(&sA[k][ty * 8 + 4]);
        float a[8] = {a0.x, a0.y, a0.z, a0.w, a1.x, a1.y, a1.z, a1.w};
        #pragma unroll
        for (int ii = 0; ii < 8; ii++) {
            ull ap = pack2(a[ii], a[ii]);
            #pragma unroll
            for (int p = 0; p < 4; p++)
                acc2[ii][p] = ffma2(ap, bp[p], acc2[ii][p]);
        }
    }

    float acc[8][8];
    #pragma unroll
    for (int ii = 0; ii < 8; ii++)
        #pragma unroll
        for (int p = 0; p < 4; p++) {
            unsigned lo, hi;
            asm("mov.b64 {%0, %1}, %2;" : "=r"(lo), "=r"(hi) : "l"(acc2[ii][p]));
            acc[ii][p * 2 + 0] = fast_sigmoid(__uint_as_float(lo));
            acc[ii][p * 2 + 1] = fast_sigmoid(__uint_as_float(hi));
        }

    // normal tile (bi,bj) — streaming stores
    #pragma unroll
    for (int ii = 0; ii < 8; ii++) {
        int gi = i0 + ty * 8 + ii;
        float4 o0 = {acc[ii][0], acc[ii][1], acc[ii][2], acc[ii][3]};
        float4 o1 = {acc[ii][4], acc[ii][5], acc[ii][6], acc[ii][7]};
        float* dst = out + (size_t)gi * N_NODES + j0 + tx * 8;
        __stcs(reinterpret_cast<float4*>(dst),     o0);
        __stcs(reinterpret_cast<float4*>(dst + 4), o1);
    }
    // mirrored tile (bj,bi)
    if (bi != bj) {
        #pragma unroll
        for (int jj = 0; jj < 8; jj++) {
            int gj = j0 + tx * 8 + jj;
            float4 o0 = {acc[0][jj], acc[1][jj], acc[2][jj], acc[3][jj]};
            float4 o1 = {acc[4][jj], acc[5][jj], acc[6][jj], acc[7][jj]};
            float* dst = out + (size_t)gj * N_NODES + i0 + ty * 8;
            __stcs(reinterpret_cast<float4*>(dst),     o0);
            __stcs(reinterpret_cast<float4*>(dst + 4), o1);
        }
    }
}

extern "C" void kernel_launch(void* const* d_in, const int* in_sizes, int n_in,
                              void* d_out, int out_size) {
    const float* X    = (const float*)d_in[0];
    const int*   erow = (const int*)  d_in[1];
    const int*   ecol = (const int*)  d_in[2];
    const float* ev   = (const float*)d_in[3];
    const float* W0   = (const float*)d_in[4];
    const float* W1   = (const float*)d_in[5];
    // d_in[6] (W2) unused: std branch is dead in eval (Z = mean)
    float* out = (float*)d_out;

    k_hist    <<<E_EDGES / 256, 256>>>(erow);
    k_scan    <<<1, 1024>>>();
    k_scatter <<<E_EDGES / 256, 256>>>(erow, ecol, ev);
    k_xw0     <<<N_NODES / 16, 512>>>(X, W0);
    k_spmm1_hw1<<<N_NODES / 8, 256>>>(W1);
    k_spmm2   <<<N_NODES / 8, 256>>>();
    const int NT = 64 * 65 / 2;   // 2080 triangular tiles
    k_decode  <<<NT, 256>>>(out);
}

// round 6
// speedup vs baseline: 1.2739x; 1.0314x over previous
#include <cuda_runtime.h>
#include <cuda_bf16.h>

#define N_NODES 8192
#define D_IN    512
#define H1      32
#define H2      16
#define E_EDGES 262144

typedef unsigned long long ull;

// -------- device-global scratch (no allocation allowed) --------
__device__ float g_xw0 [N_NODES * H1];   // X @ W0
__device__ float g_hw1 [N_NODES * H2];   // relu(spmm1) @ W1
__device__ float g_mean[N_NODES * H2];   // spmm2 result
__device__ int   g_cnt [N_NODES];        // row histogram (re-zeroed each run)
__device__ int   g_off [N_NODES + 1];    // CSR offsets
__device__ int   g_cur [N_NODES];        // scatter cursors
__device__ int2  g_edge[E_EDGES];        // (col, val bits) interleaved

// ===================== CSR build =====================
// 4 edges per thread (vector loads) -> MLP=4 on the counter atomics
__global__ void k_hist(const int* __restrict__ erow) {
    int base = (blockIdx.x * 256 + threadIdx.x) * 4;
    int4 r4 = *reinterpret_cast<const int4*>(&erow[base]);
    atomicAdd(&g_cnt[r4.x], 1);
    atomicAdd(&g_cnt[r4.y], 1);
    atomicAdd(&g_cnt[r4.z], 1);
    atomicAdd(&g_cnt[r4.w], 1);
}

__global__ void k_scan() {
    __shared__ int s[1024];
    const int t = threadIdx.x;
    const int base = t * 8;
    int loc[8], sum = 0;
    #pragma unroll
    for (int i = 0; i < 8; i++) { loc[i] = g_cnt[base + i]; sum += loc[i]; }
    s[t] = sum;
    __syncthreads();
    for (int d = 1; d < 1024; d <<= 1) {
        int v = (t >= d) ? s[t - d] : 0;
        __syncthreads();
        s[t] += v;
        __syncthreads();
    }
    int run = s[t] - sum;               // exclusive prefix
    #pragma unroll
    for (int i = 0; i < 8; i++) {
        g_off[base + i] = run;
        g_cur[base + i] = run;
        run += loc[i];
    }
    if (t == 1023) g_off[N_NODES] = run;
}

// 4 edges per thread: independent cursor-atomic chains (MLP=4)
__global__ void k_scatter(const int* __restrict__ erow, const int* __restrict__ ecol,
                          const float* __restrict__ eval) {
    int base = (blockIdx.x * 256 + threadIdx.x) * 4;
    int4   r4 = *reinterpret_cast<const int4*>(&erow[base]);
    int4   c4 = *reinterpret_cast<const int4*>(&ecol[base]);
    float4 v4 = *reinterpret_cast<const float4*>(&eval[base]);
    int p0 = atomicAdd(&g_cur[r4.x], 1);
    int p1 = atomicAdd(&g_cur[r4.y], 1);
    int p2 = atomicAdd(&g_cur[r4.z], 1);
    int p3 = atomicAdd(&g_cur[r4.w], 1);
    g_edge[p0] = make_int2(c4.x, __float_as_int(v4.x));
    g_edge[p1] = make_int2(c4.y, __float_as_int(v4.y));
    g_edge[p2] = make_int2(c4.z, __float_as_int(v4.z));
    g_edge[p3] = make_int2(c4.w, __float_as_int(v4.w));
    // cnt is dead after k_scan: re-zero for next replay (globals start zeroed)
    if (base < N_NODES)
        *reinterpret_cast<int4*>(&g_cnt[base]) = make_int4(0, 0, 0, 0);
}

// ===================== K1: g_xw0 = X @ W0 =====================
// 512 thr = 16 warps; block does 16 rows. Warp w owns k-slice [32w, 32w+32):
// its W slice lives in 32 registers (loaded once). X staged in smem (32KB),
// read as broadcast LDS.128. 16 independent row-accumulators per warp.
// Partials land in the SAME smem buffer (reused after a barrier), then reduced.
__global__ __launch_bounds__(512) void k_xw0(const float* __restrict__ X,
                                             const float* __restrict__ W0) {
    __shared__ float sbuf[16 * 512];    // 32KB: X tile, then partials [w][r][c]
    const int tid  = threadIdx.x;
    const int lane = tid & 31;
    const int wid  = tid >> 5;
    const int row0 = blockIdx.x * 16;
    const int kw   = wid * 32;          // this warp's k-slice base

    // W slice -> registers (coalesced, L2-resident, once per kernel)
    float wreg[32];
    #pragma unroll
    for (int kk = 0; kk < 32; kk++)
        wreg[kk] = W0[(size_t)(kw + kk) * H1 + lane];

    // stage X tile: 2048 float4, 4 per thread, fully coalesced
    {
        const float4* X4 = reinterpret_cast<const float4*>(X + (size_t)row0 * D_IN);
        float4* S4 = reinterpret_cast<float4*>(sbuf);
        #pragma unroll
        for (int i = 0; i < 4; i++)
            S4[tid + i * 512] = X4[tid + i * 512];
    }
    __syncthreads();

    float acc[16];
    #pragma unroll
    for (int r = 0; r < 16; r++) acc[r] = 0.f;

    #pragma unroll
    for (int kk4 = 0; kk4 < 8; kk4++) {
        const int k = kw + kk4 * 4;
        const float w0 = wreg[kk4 * 4 + 0];
        const float w1 = wreg[kk4 * 4 + 1];
        const float w2 = wreg[kk4 * 4 + 2];
        const float w3 = wreg[kk4 * 4 + 3];
        #pragma unroll
        for (int r = 0; r < 16; r++) {
            float4 xv = *reinterpret_cast<const float4*>(&sbuf[r * 512 + k]);
            acc[r] = fmaf(xv.x, w0, fmaf(xv.y, w1, fmaf(xv.z, w2, fmaf(xv.w, w3, acc[r]))));
        }
    }
    __syncthreads();                    // all x reads done; reuse sbuf as partials
    #pragma unroll
    for (int r = 0; r < 16; r++)
        sbuf[wid * 512 + r * 32 + lane] = acc[r];
    __syncthreads();

    // reduce 16 partials per output; thread (r=wid, c=lane)
    float s = 0.f;
    #pragma unroll
    for (int w = 0; w < 16; w++)
        s += sbuf[w * 512 + wid * 32 + lane];
    g_xw0[(size_t)(row0 + wid) * H1 + lane] = s;
}

// ===================== K2: fused spmm1 + relu + @W1 =====================
__global__ void k_spmm1_hw1(const float* __restrict__ W1) {
    __shared__ float sW1[H1][H2];
    __shared__ float sH[8][H1];
    const int tid  = threadIdx.x;
    const int lane = tid & 31;
    const int wid  = tid >> 5;
    for (int idx = tid; idx < H1 * H2; idx += 256)
        sW1[idx >> 4][idx & 15] = W1[idx];
    __syncthreads();

    const int row = blockIdx.x * 8 + wid;
    const int beg = g_off[row], end = g_off[row + 1];
    float acc = 0.f;
    for (int e0 = beg; e0 < end; e0 += 32) {
        int ee = e0 + lane;
        int2 ed = (ee < end) ? g_edge[ee] : make_int2(0, 0);
        int m = min(32, end - e0);   // warp-uniform
        for (int j = 0; j < m; j++) {
            int   cj = __shfl_sync(0xFFFFFFFFu, ed.x, j);
            float vj = __int_as_float(__shfl_sync(0xFFFFFFFFu, ed.y, j));
            acc = fmaf(vj, g_xw0[cj * H1 + lane], acc);
        }
    }
    sH[wid][lane] = fmaxf(acc, 0.0f);
    __syncwarp();
    if (lane < H2) {
        float o = 0.f;
        #pragma unroll
        for (int k = 0; k < H1; k++)
            o = fmaf(sH[wid][k], sW1[k][lane], o);
        g_hw1[row * H2 + lane] = o;
    }
}

// ===================== K3: spmm2 (warp per row, 2 edges/iter) =====================
__global__ void k_spmm2() {
    const int tid  = threadIdx.x;
    const int lane = tid & 31;
    const int wid  = tid >> 5;
    const int half = lane >> 4;
    const int col  = lane & 15;

    const int row = blockIdx.x * 8 + wid;
    const int beg = g_off[row], end = g_off[row + 1];
    float acc = 0.f;
    for (int e0 = beg; e0 < end; e0 += 32) {
        int ee = e0 + lane;
        int2 ed = (ee < end) ? g_edge[ee] : make_int2(0, 0);
        int m  = min(32, end - e0);
        int mp = (m + 1) & ~1;          // even trip count for both halves
        for (int j = half; j < mp; j += 2) {
            int   cj = __shfl_sync(0xFFFFFFFFu, ed.x, j);
            float vj = __int_as_float(__shfl_sync(0xFFFFFFFFu, ed.y, j));
            acc = fmaf(vj, g_hw1[cj * H2 + col], acc);
        }
    }
    acc += __shfl_xor_sync(0xFFFFFFFFu, acc, 16);
    if (lane < H2) g_mean[row * H2 + lane] = acc;
}

// ===================== fast sigmoid: MUFU ex2 + MUFU rcp =====================
__device__ __forceinline__ float fast_sigmoid(float x) {
    float t = fabsf(x) * -1.4426950408889634f;
    float e; asm("ex2.approx.f32 %0, %1;" : "=f"(e) : "f"(t));
    float d = 1.0f + e;
    float r; asm("rcp.approx.f32 %0, %1;" : "=f"(r) : "f"(d));
    return (x > 0.0f) ? r : e * r;
}

// packed fp32x2 fma (sm_103a FFMA2, PTX-only)
__device__ __forceinline__ ull ffma2(ull a, ull b, ull c) {
    ull d;
    asm("fma.rn.f32x2 %0, %1, %2, %3;" : "=l"(d) : "l"(a), "l"(b), "l"(c));
    return d;
}
__device__ __forceinline__ ull pack2(float lo, float hi) {
    ull d;
    asm("mov.b64 %0, {%1, %2};" : "=l"(d) : "r"(__float_as_uint(lo)), "r"(__float_as_uint(hi)));
    return d;
}

// ===================== K4: decode A = sigmoid(Z Z^T) =====================
__global__ __launch_bounds__(256) void k_decode(float* __restrict__ out) {
    const int t = blockIdx.x;
    int i = (int)((sqrtf(8.0f * (float)t + 1.0f) - 1.0f) * 0.5f);
    int j = t - ((i * (i + 1)) >> 1);
    if (j < 0)  { i--; j = t - ((i * (i + 1)) >> 1); }
    if (j > i)  { i++; j = t - ((i * (i + 1)) >> 1); }
    const int bi = j, bj = i;

    __shared__ float sA[H2][132];
    __shared__ float sB[H2][132];
    const int tid = threadIdx.x;
    const int i0 = bi * 128, j0 = bj * 128;

    for (int idx = tid; idx < 128 * H2; idx += 256) {
        int r = idx >> 4, c = idx & 15;
        sA[c][r] = fmaxf(g_mean[(i0 + r) * H2 + c], 1e-32f);
        sB[c][r] = fmaxf(g_mean[(j0 + r) * H2 + c], 1e-32f);
    }
    __syncthreads();

    const int tx = tid & 15, ty = tid >> 4;
    ull acc2[8][4];
    #pragma unroll
    for (int ii = 0; ii < 8; ii++)
        #pragma unroll
        for (int p = 0; p < 4; p++) acc2[ii][p] = 0ull;

    #pragma unroll
    for (int k = 0; k < H2; k++) {
        ulonglong2 bq0 = *reinterpret_cast<const ulonglong2*>(&sB[k][tx * 8]);
        ulonglong2 bq1 = *reinterpret_cast<const ulonglong2*>(&sB[k][tx * 8 + 4]);
        ull bp[4] = {bq0.x, bq0.y, bq1.x, bq1.y};
        float4 a0 = *reinterpret_cast<const float4*>(&sA[k][ty * 8]);
        float4 a1 = *reinterpret_cast<const float4*>(&sA[k][ty * 8 + 4]);
        float a[8] = {a0.x, a0.y, a0.z, a0.w, a1.x, a1.y, a1.z, a1.w};
        #pragma unroll
        for (int ii = 0; ii < 8; ii++) {
            ull ap = pack2(a[ii], a[ii]);
            #pragma unroll
            for (int p = 0; p < 4; p++)
                acc2[ii][p] = ffma2(ap, bp[p], acc2[ii][p]);
        }
    }

    float acc[8][8];
    #pragma unroll
    for (int ii = 0; ii < 8; ii++)
        #pragma unroll
        for (int p = 0; p < 4; p++) {
            unsigned lo, hi;
            asm("mov.b64 {%0, %1}, %2;" : "=r"(lo), "=r"(hi) : "l"(acc2[ii][p]));
            acc[ii][p * 2 + 0] = fast_sigmoid(__uint_as_float(lo));
            acc[ii][p * 2 + 1] = fast_sigmoid(__uint_as_float(hi));
        }

    // normal tile (bi,bj) — streaming stores
    #pragma unroll
    for (int ii = 0; ii < 8; ii++) {
        int gi = i0 + ty * 8 + ii;
        float4 o0 = {acc[ii][0], acc[ii][1], acc[ii][2], acc[ii][3]};
        float4 o1 = {acc[ii][4], acc[ii][5], acc[ii][6], acc[ii][7]};
        float* dst = out + (size_t)gi * N_NODES + j0 + tx * 8;
        __stcs(reinterpret_cast<float4*>(dst),     o0);
        __stcs(reinterpret_cast<float4*>(dst + 4), o1);
    }
    // mirrored tile (bj,bi)
    if (bi != bj) {
        #pragma unroll
        for (int jj = 0; jj < 8; jj++) {
            int gj = j0 + tx * 8 + jj;
            float4 o0 = {acc[0][jj], acc[1][jj], acc[2][jj], acc[3][jj]};
            float4 o1 = {acc[4][jj], acc[5][jj], acc[6][jj], acc[7][jj]};
            float* dst = out + (size_t)gj * N_NODES + i0 + ty * 8;
            __stcs(reinterpret_cast<float4*>(dst),     o0);
            __stcs(reinterpret_cast<float4*>(dst + 4), o1);
        }
    }
}

extern "C" void kernel_launch(void* const* d_in, const int* in_sizes, int n_in,
                              void* d_out, int out_size) {
    const float* X    = (const float*)d_in[0];
    const int*   erow = (const int*)  d_in[1];
    const int*   ecol = (const int*)  d_in[2];
    const float* ev   = (const float*)d_in[3];
    const float* W0   = (const float*)d_in[4];
    const float* W1   = (const float*)d_in[5];
    // d_in[6] (W2) unused: std branch is dead in eval (Z = mean)
    float* out = (float*)d_out;

    k_hist    <<<E_EDGES / 1024, 256>>>(erow);
    k_scan    <<<1, 1024>>>();
    k_scatter <<<E_EDGES / 1024, 256>>>(erow, ecol, ev);
    k_xw0     <<<N_NODES / 16, 512>>>(X, W0);
    k_spmm1_hw1<<<N_NODES / 8, 256>>>(W1);
    k_spmm2   <<<N_NODES / 8, 256>>>();
    const int NT = 64 * 65 / 2;   // 2080 triangular tiles
    k_decode  <<<NT, 256>>>(out);
}